// round 12
// baseline (speedup 1.0000x reference)
#include <cuda_runtime.h>

// Problem constants
#define NB   16        // batches
#define NPB  262144    // elements per batch (512*512)
#define HB   64        // histogram bins
#define HC   64        // hist CTAs per batch
#define HT   128       // hist threads per CTA
#define MC   16        // minmax CTAs per batch

#define KL_EPS 1e-8f
#define WEIGHT 0.1f

// ---------------- device scratch (no allocations allowed) ----------------
__device__ float g_pmin[NB][MC];
__device__ float g_pmax[NB][MC];
__device__ float g_part[NB][2][HC][HB];   // [batch][target=0/pred=1][cta][bin]

// ---------------- kernel 1: per-batch min/max partials (no atomics) ----------------
__global__ void __launch_bounds__(256) k_minmax(const float* __restrict__ target) {
    const int b = blockIdx.y;
    const float4* base = reinterpret_cast<const float4*>(target)
                         + (size_t)b * (NPB / 4) + (size_t)blockIdx.x * (NPB / 4 / MC);
    float lo = __int_as_float(0x7f800000);   // +inf
    float hi = __int_as_float(0xff800000);   // -inf
    #pragma unroll 8
    for (int i = threadIdx.x; i < NPB / 4 / MC; i += 256) {
        float4 v = base[i];
        lo = fminf(lo, fminf(fminf(v.x, v.y), fminf(v.z, v.w)));
        hi = fmaxf(hi, fmaxf(fmaxf(v.x, v.y), fmaxf(v.z, v.w)));
    }
    #pragma unroll
    for (int o = 16; o; o >>= 1) {
        lo = fminf(lo, __shfl_xor_sync(0xffffffffu, lo, o));
        hi = fmaxf(hi, __shfl_xor_sync(0xffffffffu, hi, o));
    }
    __shared__ float slo[8], shi[8];
    int w = threadIdx.x >> 5;
    if ((threadIdx.x & 31) == 0) { slo[w] = lo; shi[w] = hi; }
    __syncthreads();
    if (threadIdx.x == 0) {
        #pragma unroll
        for (int k = 1; k < 8; k++) { lo = fminf(lo, slo[k]); hi = fmaxf(hi, shi[k]); }
        g_pmin[b][blockIdx.x] = lo;
        g_pmax[b][blockIdx.x] = hi;
    }
}

// ---------------- kernel 2: soft histograms ----------------
// Gaussian KDE, sigma = 1 bin, 15-bin truncated window (|d| <= 7.5).
// 13-bin measurably raised final rel_err to 7e-4 (KL cancellation amplifies
// truncation bias ~3000x); 15-bin puts truncation ~2e-5, below the fp32
// rounding floor (~3e-4 final).
// CENTER-OUT recurrence seeded with precise expf at the max-weight center bin:
//   up:   g *= r,  r0 = exp(c - 0.5),  r *= e^-1
//   down: g *= q,  q0 = exp(-c - 0.5), q *= e^-1
// Per-thread SMEM histograms hist[bin*HT + tid] -> bank-conflict-free, no atomics.
__global__ void __launch_bounds__(HT) k_hist(const float* __restrict__ pred,
                                             const float* __restrict__ target) {
    __shared__ float hist[HB * HT];   // 32 KB
    __shared__ float s_vmin, s_scale;
    const int b   = blockIdx.y;
    const int c0  = blockIdx.x;
    const int tid = threadIdx.x;
    const float EINV = 0.36787944117144233f;  // e^-1

    if (tid == 0) {
        float lo = g_pmin[b][0], hi = g_pmax[b][0];
        #pragma unroll
        for (int k = 1; k < MC; k++) {
            lo = fminf(lo, g_pmin[b][k]);
            hi = fmaxf(hi, g_pmax[b][k]);
        }
        s_vmin  = lo;
        s_scale = 64.0f / (hi - lo + KL_EPS);
    }

    #pragma unroll 1
    for (int phase = 0; phase < 2; phase++) {
        const float* src = (phase == 0) ? target : pred;
        const float4* base = reinterpret_cast<const float4*>(src)
                             + (size_t)b * (NPB / 4) + (size_t)c0 * (NPB / 4 / HC);

        #pragma unroll
        for (int j = 0; j < HB; j++) hist[j * HT + tid] = 0.0f;
        __syncthreads();

        const float vmin  = s_vmin;
        const float scale = s_scale;

        #pragma unroll 1
        for (int i = tid; i < NPB / 4 / HC; i += HT) {
            float4 v = base[i];
            float xs[4] = {v.x, v.y, v.z, v.w};
            #pragma unroll
            for (int e = 0; e < 4; e++) {
                float u  = (xs[e] - vmin) * scale;   // position in bin units
                float jf = floorf(u);
                int   jc = (int)jf;                  // center bin (contains u)
                float c  = u - jf - 0.5f;            // offset from center bin's center
                float g0 = expf(-0.5f * c * c);
                float r  = expf(c - 0.5f);           // upward ratio seed
                float q  = expf(-c - 0.5f);          // downward ratio seed

                if ((unsigned)jc < (unsigned)HB) hist[jc * HT + tid] += g0;
                float gu = g0, gd = g0;
                #pragma unroll
                for (int m = 1; m <= 7; m++) {
                    gu *= r;
                    int ju = jc + m;
                    if ((unsigned)ju < (unsigned)HB) hist[ju * HT + tid] += gu;
                    r *= EINV;
                    gd *= q;
                    int jd = jc - m;
                    if ((unsigned)jd < (unsigned)HB) hist[jd * HT + tid] += gd;
                    q *= EINV;
                }
            }
        }
        __syncthreads();

        // reduce 128 per-thread slices -> 64 bins (rotated, conflict-free)
        if (tid < HB) {
            const int bin = tid;
            float s0 = 0.f, s1 = 0.f, s2 = 0.f, s3 = 0.f;
            #pragma unroll 4
            for (int s = 0; s < HT; s += 4) {
                s0 += hist[bin * HT + ((s + 0 + bin) & (HT - 1))];
                s1 += hist[bin * HT + ((s + 1 + bin) & (HT - 1))];
                s2 += hist[bin * HT + ((s + 2 + bin) & (HT - 1))];
                s3 += hist[bin * HT + ((s + 3 + bin) & (HT - 1))];
            }
            g_part[b][phase][c0][bin] = (s0 + s1) + (s2 + s3);
        }
        __syncthreads();
    }
}

// ---------------- kernel 3: fused tail (CTA-partial reduce + KL + output) ----------------
// Single CTA, 1024 threads = 32 warps. Warp w handles (batch, phase) = (w>>1, w&1):
// lanes hold float2 bin-pairs, sum over the 64 CTA partials with coalesced,
// L2-resident loads in fixed c order. Then shfl-butterfly batch sums, KL terms,
// and a fixed-shape shfl+smem tree. Deterministic: every sum has a fixed dataflow.
__global__ void __launch_bounds__(1024) k_tail(float* __restrict__ out) {
    __shared__ float hsum[NB][2][HB];   // 8 KB
    __shared__ float recp[NB][2];
    __shared__ float wsum[32];
    const int tid  = threadIdx.x;
    const int w    = tid >> 5;          // 0..31 -> (b,p)
    const int lane = tid & 31;
    const int wb   = w >> 1;
    const int wp   = w & 1;

    // stage 1: sum over HC cta-partials (stride HB floats between c's; lanes
    // cover 32 consecutive float2 -> 256B coalesced per step)
    const float2* src = reinterpret_cast<const float2*>(&g_part[wb][wp][0][0]) + lane;
    float sx = 0.f, sy = 0.f;
    #pragma unroll 8
    for (int c = 0; c < HC; c++) {
        float2 v = src[(size_t)c * (HB / 2)];
        sx += v.x; sy += v.y;
    }
    hsum[wb][wp][lane * 2]     = sx;
    hsum[wb][wp][lane * 2 + 1] = sy;

    // per-(b,p) total via warp butterfly (fixed dataflow)
    float tot = sx + sy;
    #pragma unroll
    for (int o = 16; o; o >>= 1) tot += __shfl_xor_sync(0xffffffffu, tot, o);
    if (lane == 0) recp[wb][wp] = 1.0f / (tot + KL_EPS);
    __syncthreads();

    // stage 2: KL terms, one per (batch, bin)
    const int b = tid >> 6;
    const int j = tid & (HB - 1);
    const float tp = hsum[b][0][j] * recp[b][0];
    const float pp = hsum[b][1][j] * recp[b][1];
    float term = tp * (logf(tp + KL_EPS) - logf(pp + KL_EPS));

    // stage 3: reduce 1024 terms (warp butterfly + cross-warp)
    #pragma unroll
    for (int o = 16; o; o >>= 1) term += __shfl_xor_sync(0xffffffffu, term, o);
    if (lane == 0) wsum[w] = term;
    __syncthreads();
    if (w == 0) {
        float v = wsum[lane];
        #pragma unroll
        for (int o = 16; o; o >>= 1) v += __shfl_xor_sync(0xffffffffu, v, o);
        if (lane == 0) out[0] = WEIGHT * (v / (float)NB);
    }
}

// ---------------- launch ----------------
extern "C" void kernel_launch(void* const* d_in, const int* in_sizes, int n_in,
                              void* d_out, int out_size) {
    const float* pred   = (const float*)d_in[0];
    const float* target = (const float*)d_in[1];
    float* out = (float*)d_out;

    k_minmax<<<dim3(MC, NB), 256>>>(target);
    k_hist  <<<dim3(HC, NB), HT>>>(pred, target);
    k_tail  <<<1, 1024>>>(out);
}